// round 4
// baseline (speedup 1.0000x reference)
#include <cuda_runtime.h>
#include <math.h>

#define N_NODES 8192
#define IN_F    256
#define HID     256
#define ALPHA   0.2f

// Scratch (no allocations allowed). 16B-aligned: read through float4*.
__device__ __align__(16) float g_s1[N_NODES];
__device__ __align__(16) float g_s2[N_NODES];

// ---------------------------------------------------------------------------
// Gate-free prologue. Every block redundantly computes u1=W@a1, u2=W@a2 into
// smem (W: 256KB, L2-resident after the first block touches it), then computes
// s1/s2 = src@u1 / src@u2 for its strided share of rows. No inter-block sync.
// ---------------------------------------------------------------------------
#define PRO_BLOCKS 128
__global__ void __launch_bounds__(256)
prologue_kernel(const float* __restrict__ W,
                const float* __restrict__ a,
                const float* __restrict__ src) {
    __shared__ float sa1[HID], sa2[HID];
    __shared__ __align__(16) float su1[IN_F], su2[IN_F];

    const int t    = threadIdx.x;
    const int lane = t & 31;
    const int wid  = t >> 5;

    sa1[t] = __ldg(a + t);
    sa2[t] = __ldg(a + HID + t);
    __syncthreads();

    // u[t] = W[t,:] . a  — thread t streams its own W row (L1/L2 cached).
    {
        const float4* wrow = (const float4*)(W + (size_t)t * HID);
        float d1 = 0.f, d2 = 0.f;
        #pragma unroll 8
        for (int j = 0; j < HID / 4; j++) {
            float4 w = wrow[j];
            int k = j * 4;
            d1 += w.x * sa1[k] + w.y * sa1[k+1] + w.z * sa1[k+2] + w.w * sa1[k+3];
            d2 += w.x * sa2[k] + w.y * sa2[k+1] + w.z * sa2[k+2] + w.w * sa2[k+3];
        }
        su1[t] = d1;
        su2[t] = d2;
    }
    __syncthreads();

    // s1/s2: warp per src row, rows strided across the grid.
    const float4* su1v = (const float4*)su1;
    const float4* su2v = (const float4*)su2;
    for (int row = blockIdx.x * 8 + wid; row < N_NODES; row += PRO_BLOCKS * 8) {
        const float4* srow = (const float4*)(src + (size_t)row * IN_F);
        float d1 = 0.f, d2 = 0.f;
        #pragma unroll
        for (int k = 0; k < 2; k++) {
            int idx = lane + k * 32;          // float4 index 0..63
            float4 v  = srow[idx];
            float4 u1 = su1v[idx];
            float4 u2 = su2v[idx];
            d1 += v.x * u1.x + v.y * u1.y + v.z * u1.z + v.w * u1.w;
            d2 += v.x * u2.x + v.y * u2.y + v.z * u2.z + v.w * u2.w;
        }
        #pragma unroll
        for (int o = 16; o; o >>= 1) {
            d1 += __shfl_xor_sync(0xFFFFFFFFu, d1, o);
            d2 += __shfl_xor_sync(0xFFFFFFFFu, d2, o);
        }
        if (lane == 0) { g_s1[row] = d1; g_s2[row] = d2; }
    }
}

// ---------------------------------------------------------------------------
// Fused e-compute + row softmax. One block (512 thr) per row; each thread
// holds 4 float4 (16 floats) -> low reg pressure -> 3 blocks/SM (75% occ),
// more loads in flight and better cross-block phase overlap than the
// previous 256-thr/64-reg version. One read (bias, .cs) + one write (.cs)
// per element.
// ---------------------------------------------------------------------------
__global__ void __launch_bounds__(512, 3)
softmax_kernel(const float* __restrict__ bias, float* __restrict__ out) {
    __shared__ float shm[16];
    __shared__ float shs[16];

    const int row  = blockIdx.x;
    const int t    = threadIdx.x;
    const int lane = t & 31;
    const int wid  = t >> 5;

    const float s1 = g_s1[row];
    const float4* __restrict__ brow = (const float4*)(bias + (size_t)row * N_NODES);
    const float4* __restrict__ s2v  = (const float4*)g_s2;

    float4 e[4];
    float lmax = -INFINITY;
    #pragma unroll
    for (int k = 0; k < 4; k++) {
        const int idx = t + k * 512;      // coalesced float4 index within row
        float4 b  = __ldcs(brow + idx);   // streaming read-once
        float4 s2 = s2v[idx];             // default .ca: hot in L1
        float v;
        v = s1 + s2.x; v = v > 0.f ? v : ALPHA * v; b.x += v;
        v = s1 + s2.y; v = v > 0.f ? v : ALPHA * v; b.y += v;
        v = s1 + s2.z; v = v > 0.f ? v : ALPHA * v; b.z += v;
        v = s1 + s2.w; v = v > 0.f ? v : ALPHA * v; b.w += v;
        e[k] = b;
        lmax = fmaxf(lmax, fmaxf(fmaxf(b.x, b.y), fmaxf(b.z, b.w)));
    }

    // block-reduce max (16 warps)
    #pragma unroll
    for (int o = 16; o; o >>= 1)
        lmax = fmaxf(lmax, __shfl_xor_sync(0xFFFFFFFFu, lmax, o));
    if (lane == 0) shm[wid] = lmax;
    __syncthreads();
    float rmax = shm[0];
    #pragma unroll
    for (int i = 1; i < 16; i++) rmax = fmaxf(rmax, shm[i]);

    // exp in-register + block-reduce sum
    float lsum = 0.f;
    #pragma unroll
    for (int k = 0; k < 4; k++) {
        e[k].x = __expf(e[k].x - rmax);
        e[k].y = __expf(e[k].y - rmax);
        e[k].z = __expf(e[k].z - rmax);
        e[k].w = __expf(e[k].w - rmax);
        lsum += (e[k].x + e[k].y) + (e[k].z + e[k].w);
    }
    #pragma unroll
    for (int o = 16; o; o >>= 1)
        lsum += __shfl_xor_sync(0xFFFFFFFFu, lsum, o);
    if (lane == 0) shs[wid] = lsum;
    __syncthreads();
    float rsum = 0.f;
    #pragma unroll
    for (int i = 0; i < 16; i++) rsum += shs[i];
    const float inv = 1.0f / rsum;

    float4* __restrict__ orow = (float4*)(out + (size_t)row * N_NODES);
    #pragma unroll
    for (int k = 0; k < 4; k++) {
        float4 v = e[k];
        v.x *= inv; v.y *= inv; v.z *= inv; v.w *= inv;
        __stcs(orow + t + k * 512, v);    // streaming store
    }
}

// ---------------------------------------------------------------------------
extern "C" void kernel_launch(void* const* d_in, const int* in_sizes, int n_in,
                              void* d_out, int out_size) {
    const float* src  = nullptr;
    const float* bias = nullptr;
    const float* W    = nullptr;
    const float* a    = nullptr;
    for (int i = 0; i < n_in; i++) {
        switch (in_sizes[i]) {
            case N_NODES * IN_F:    src  = (const float*)d_in[i]; break; // 2097152
            case 67108864:          bias = (const float*)d_in[i]; break; // N*N
            case IN_F * HID:        W    = (const float*)d_in[i]; break; // 65536
            case 2 * HID:           a    = (const float*)d_in[i]; break; // 512
            default: break;
        }
    }
    float* out = (float*)d_out;

    prologue_kernel<<<PRO_BLOCKS, 256>>>(W, a, src);
    softmax_kernel<<<N_NODES, 512>>>(bias, out);
    (void)out_size;
}